// round 4
// baseline (speedup 1.0000x reference)
#include <cuda_runtime.h>
#include <cuda_bf16.h>
#include <math.h>

#define N 512
#define D 512
#define MARGIN 0.3f
#define EPSF 1e-12f

// Scratch (no cudaMalloc allowed)
__device__ float g_sq[N];
__device__ float g_dist[N * N];
__device__ float g_partial_loss[N];
__device__ int   g_partial_cnt[N];

// ---------------------------------------------------------------------------
// Kernel 1: row squared norms. One block per row, 128 threads, float4 loads.
// ---------------------------------------------------------------------------
__global__ __launch_bounds__(128) void sq_kernel(const float* __restrict__ A) {
    int r = blockIdx.x;
    const float4* row = (const float4*)(A + r * D);
    float s = 0.f;
    // D/4 = 128 float4 per row, one per thread
    float4 v = row[threadIdx.x];
    s = v.x * v.x + v.y * v.y + v.z * v.z + v.w * v.w;
    for (int o = 16; o > 0; o >>= 1) s += __shfl_down_sync(0xffffffffu, s, o);
    __shared__ float ws[4];
    if ((threadIdx.x & 31) == 0) ws[threadIdx.x >> 5] = s;
    __syncthreads();
    if (threadIdx.x == 0) g_sq[r] = ws[0] + ws[1] + ws[2] + ws[3];
}

// ---------------------------------------------------------------------------
// Kernel 2: pairwise distances. 64x64 tile per block, 256 threads,
// 4x4 register micro-tile, k-major smem, LDS.128 operand reads.
// ---------------------------------------------------------------------------
#define BM 64
#define BN 64
#define BK 16

__global__ __launch_bounds__(256) void dist_kernel(const float* __restrict__ A) {
    __shared__ float As[BK][BM + 4];
    __shared__ float Bs[BK][BN + 4];

    int tid = threadIdx.x;
    int tx = tid & 15;   // micro-tile col group (0..15)
    int ty = tid >> 4;   // micro-tile row group (0..15)
    int m0 = blockIdx.y * BM;
    int n0 = blockIdx.x * BN;

    // Cooperative load mapping: thread -> (row 0..63, float4-slot 0..3 along k)
    int lrow = tid >> 2;
    int lk4  = (tid & 3) * 4;

    float acc[4][4] = {};

    for (int k0 = 0; k0 < D; k0 += BK) {
        float4 av = *(const float4*)&A[(m0 + lrow) * D + k0 + lk4];
        float4 bv = *(const float4*)&A[(n0 + lrow) * D + k0 + lk4];
        As[lk4 + 0][lrow] = av.x;
        As[lk4 + 1][lrow] = av.y;
        As[lk4 + 2][lrow] = av.z;
        As[lk4 + 3][lrow] = av.w;
        Bs[lk4 + 0][lrow] = bv.x;
        Bs[lk4 + 1][lrow] = bv.y;
        Bs[lk4 + 2][lrow] = bv.z;
        Bs[lk4 + 3][lrow] = bv.w;
        __syncthreads();
#pragma unroll
        for (int k = 0; k < BK; k++) {
            float4 a4 = *(const float4*)&As[k][ty * 4];
            float4 b4 = *(const float4*)&Bs[k][tx * 4];
            float a[4] = {a4.x, a4.y, a4.z, a4.w};
            float b[4] = {b4.x, b4.y, b4.z, b4.w};
#pragma unroll
            for (int i = 0; i < 4; i++)
#pragma unroll
                for (int j = 0; j < 4; j++)
                    acc[i][j] = fmaf(a[i], b[j], acc[i][j]);
        }
        __syncthreads();
    }

    int colb = n0 + tx * 4;
    float sc0 = g_sq[colb + 0], sc1 = g_sq[colb + 1];
    float sc2 = g_sq[colb + 2], sc3 = g_sq[colb + 3];
#pragma unroll
    for (int i = 0; i < 4; i++) {
        int row = m0 + ty * 4 + i;
        float sr = g_sq[row];
        float4 o;
        o.x = sqrtf(fmaxf(sr + sc0 - 2.f * acc[i][0], EPSF));
        o.y = sqrtf(fmaxf(sr + sc1 - 2.f * acc[i][1], EPSF));
        o.z = sqrtf(fmaxf(sr + sc2 - 2.f * acc[i][2], EPSF));
        o.w = sqrtf(fmaxf(sr + sc3 - 2.f * acc[i][3], EPSF));
        *(float4*)&g_dist[row * N + colb] = o;
    }
}

// ---------------------------------------------------------------------------
// Kernel 3: per-anchor batch-all triplet partial sums. One block per anchor.
// Deterministic: each block writes its own slot (no float atomics).
// ---------------------------------------------------------------------------
__global__ __launch_bounds__(256) void loss_kernel(const int* __restrict__ targets) {
    int i = blockIdx.x;
    int tid = threadIdx.x;

    __shared__ float drow[N];
    __shared__ float posv[N];
    __shared__ int   npos_sh;
    __shared__ int   tgt_sh[N];

    if (tid == 0) npos_sh = 0;
    for (int j = tid; j < N; j += 256) {
        drow[j]   = g_dist[i * N + j];
        tgt_sh[j] = targets[j];
    }
    __syncthreads();

    int ti = tgt_sh[i];
    // Positive-distance list (diagonal included, matching reference).
    for (int j = tid; j < N; j += 256) {
        if (tgt_sh[j] == ti) {
            int p = atomicAdd(&npos_sh, 1);
            posv[p] = drow[j];
        }
    }
    __syncthreads();
    int np = npos_sh;
    int nn = N - np;

    float sum = 0.f;
    for (int j = tid; j < N; j += 256) {
        if (tgt_sh[j] != ti) {
            float base = MARGIN - drow[j];
            for (int p = 0; p < np; p++) {
                sum += fmaxf(posv[p] + base, 0.f);
            }
        }
    }
    for (int o = 16; o > 0; o >>= 1) sum += __shfl_down_sync(0xffffffffu, sum, o);
    __shared__ float ws[8];
    if ((tid & 31) == 0) ws[tid >> 5] = sum;
    __syncthreads();
    if (tid == 0) {
        float t = 0.f;
#pragma unroll
        for (int w = 0; w < 8; w++) t += ws[w];
        g_partial_loss[i] = t;
        g_partial_cnt[i]  = np * nn;
    }
}

// ---------------------------------------------------------------------------
// Kernel 4: final reduction over 512 anchor partials.
// ---------------------------------------------------------------------------
__global__ __launch_bounds__(512) void reduce_kernel(float* __restrict__ out) {
    int tid = threadIdx.x;
    float s = g_partial_loss[tid];
    long long c = (long long)g_partial_cnt[tid];
    for (int o = 16; o > 0; o >>= 1) {
        s += __shfl_down_sync(0xffffffffu, s, o);
        c += __shfl_down_sync(0xffffffffu, c, o);
    }
    __shared__ float ws[16];
    __shared__ long long wc[16];
    if ((tid & 31) == 0) { ws[tid >> 5] = s; wc[tid >> 5] = c; }
    __syncthreads();
    if (tid == 0) {
        float ts = 0.f;
        long long tc = 0;
#pragma unroll
        for (int w = 0; w < 16; w++) { ts += ws[w]; tc += wc[w]; }
        out[0] = ts / (float)tc;
    }
}

extern "C" void kernel_launch(void* const* d_in, const int* in_sizes, int n_in,
                              void* d_out, int out_size) {
    const float* A       = (const float*)d_in[0];
    const int*   targets = (const int*)d_in[1];
    float*       out     = (float*)d_out;

    sq_kernel<<<N, 128>>>(A);
    dim3 grd(N / BN, N / BM);
    dist_kernel<<<grd, 256>>>(A);
    loss_kernel<<<N, 256>>>(targets);
    reduce_kernel<<<1, 512>>>(out);
}